// round 15
// baseline (speedup 1.0000x reference)
#include <cuda_runtime.h>
#include <cuda_bf16.h>

typedef unsigned long long ull;

#define NB 2
#define NPB 4096
#define NTOT (NB*NPB)
#define JSPLIT 16
#define JRANGE (NPB/JSPLIT)   // 256
#define JT 128                // j rows staged in smem per step

// ---------------- scratch ----------------
__device__ float g_y[NTOT*64];
__device__ float g_sq[NTOT];
__device__ int   g_nbr[NTOT*7];
__device__ ull   g_part[NTOT*JSPLIT*7];   // partial top-7 keys
__device__ float g_h0[NTOT*64], g_h1[NTOT*64];
__device__ float g_f10[NTOT], g_f20[NTOT], g_f11[NTOT], g_f21[NTOT];
__device__ float g_ho[NTOT*64];
__device__ float g_f1o[NTOT], g_f2o[NTOT];
__device__ float g_outn[NTOT*64];
__device__ float g_wt[9*64*64];      // convT weights [k][ci][co]
__device__ float g_wc[31*9*64];      // conv-head weights [ci*9+k][co]
__device__ float g_va[4*64];         // folded attention vecs heads 0/1
__device__ float g_vaO[2*128];       // folded attention vecs out head

__device__ __forceinline__ ull fma2(ull a, ull b, ull c) {
    ull d;
    asm("fma.rn.f32x2 %0, %1, %2, %3;" : "=l"(d) : "l"(a), "l"(b), "l"(c));
    return d;
}
__device__ __forceinline__ float sum2(ull v) {
    return __uint_as_float((unsigned)(v & 0xffffffffull))
         + __uint_as_float((unsigned)(v >> 32));
}
__device__ __forceinline__ ull dup2(float v) {
    ull r;
    asm("mov.b64 %0, {%1, %1};" : "=l"(r) : "r"(__float_as_uint(v)));
    return r;
}
__device__ __forceinline__ float lo2(ull v) { return __uint_as_float((unsigned)(v & 0xffffffffull)); }
__device__ __forceinline__ float hi2(ull v) { return __uint_as_float((unsigned)(v >> 32)); }

// ---------------- K0: prep (repacks + folded attention vectors) ----------------
__global__ void prep_kernel(const float* __restrict__ w_last,
                            const float* __restrict__ w_head,
                            const float* __restrict__ W0, const float* __restrict__ a0,
                            const float* __restrict__ W1, const float* __restrict__ a1,
                            const float* __restrict__ W_out, const float* __restrict__ a_out) {
    int idx = blockIdx.x * 256 + threadIdx.x;
    if (idx < 36864) {
        int co = idx & 63, ci = (idx >> 6) & 63, k = idx >> 12;
        g_wt[(k*64 + ci)*64 + co] = w_last[(ci*64 + co)*9 + k];
    } else if (idx < 36864 + 17856) {
        int j = idx - 36864;          // j = (ci*9+k)*64+co
        int co = j & 63, rest = j >> 6;
        int k = rest % 9, ci = rest / 9;
        g_wc[j] = w_head[(co*31 + ci)*9 + k];
    } else if (idx < 36864 + 17856 + 256) {
        int j = idx - 54720;
        int head = j >> 7, which = (j >> 6) & 1, k = j & 63;
        const float* W = head ? W1 : W0;
        const float* a = head ? a1 : a0;
        float s = 0.f;
        for (int c = 0; c < 64; c++) s += W[k*64 + c] * a[which*64 + c];
        g_va[(head*2 + which)*64 + k] = s;
    } else if (idx < 36864 + 17856 + 512) {
        int j = idx - 54976;
        int which = j >> 7, k = j & 127;
        float s = 0.f;
        for (int c = 0; c < 64; c++) s += W_out[k*64 + c] * a_out[which*64 + c];
        g_vaO[which*128 + k] = s;
    }
}

// ---------------- K1: fused conv head + squared norms + proj heads 0/1 ----------------
__global__ void conv_proj_kernel(const float* __restrict__ x,
                                 const float* __restrict__ bias,
                                 const float* __restrict__ W0,
                                 const float* __restrict__ W1) {
    __shared__ float ys[32*68];       // 8,704 B  (y slab, node-major)
    __shared__ float buf[64*136];     // 34,816 B (union: sIn / Wc)
    int blk = blockIdx.x;             // b(1) | oh(6) | half(1)
    int b = blk >> 7;
    int oh = (blk >> 1) & 63;
    int half = blk & 1;
    int ow0 = half * 32;
    int t = threadIdx.x;              // 256

    for (int idx = t; idx < 31*3*66; idx += 256) {
        int iwp = idx % 66;
        int rem = idx / 66;
        int r = rem % 3, ci = rem / 3;
        int ih = oh*2 - 1 + r, iw = ow0*2 - 1 + iwp;
        float v = 0.f;
        if ((unsigned)ih < 128u && (unsigned)iw < 128u)
            v = x[((b*31 + ci)*128 + ih)*128 + iw];
        buf[idx] = v;
    }
    __syncthreads();

    // conv phase, f32x2-packed accumulators
    int cog = t & 15, owg = t >> 4;
    ull accP[2][2];
    #pragma unroll
    for (int q = 0; q < 2; q++) { accP[q][0] = 0ull; accP[q][1] = 0ull; }
    for (int ci = 0; ci < 31; ci++) {
        #pragma unroll
        for (int r = 0; r < 3; r++) {
            int ib = (ci*3 + r)*66 + owg*4;
            #pragma unroll
            for (int kw = 0; kw < 3; kw++) {
                ulonglong2 wv = *(const ulonglong2*)&g_wc[((ci*9 + r*3 + kw)*64) + cog*4];
                #pragma unroll
                for (int q = 0; q < 2; q++) {
                    ull iv = dup2(buf[ib + 2*q + kw]);
                    accP[q][0] = fma2(iv, wv.x, accP[q][0]);
                    accP[q][1] = fma2(iv, wv.y, accP[q][1]);
                }
            }
        }
    }
    float4 bv = *(const float4*)&bias[cog*4];
    float ssq[2];
    #pragma unroll
    for (int q = 0; q < 2; q++) {
        int node = b*4096 + oh*64 + ow0 + owg*2 + q;
        float4 o;
        o.x = lo2(accP[q][0]) + bv.x; o.y = hi2(accP[q][0]) + bv.y;
        o.z = lo2(accP[q][1]) + bv.z; o.w = hi2(accP[q][1]) + bv.w;
        *(float4*)&g_y[node*64 + cog*4] = o;
        *(float4*)&ys[(owg*2 + q)*68 + cog*4] = o;
        ssq[q] = o.x*o.x + o.y*o.y + o.z*o.z + o.w*o.w;
    }
    #pragma unroll
    for (int off = 1; off <= 8; off <<= 1)
        #pragma unroll
        for (int q = 0; q < 2; q++)
            ssq[q] += __shfl_xor_sync(0xffffffffu, ssq[q], off);
    if (cog == 0) {
        #pragma unroll
        for (int q = 0; q < 2; q++)
            g_sq[b*4096 + oh*64 + ow0 + owg*2 + q] = ssq[q];
    }
    __syncthreads();

    for (int idx = t; idx < 64*136; idx += 256) {
        int k = idx / 136, c = idx % 136;
        float v = 0.f;
        if (c < 64) v = W0[k*64 + c];
        else if (c < 128) v = W1[k*64 + c - 64];
        else if (c < 132) v = g_va[(c - 128)*64 + k];
        buf[idx] = v;
    }
    __syncthreads();

    int i0 = b*4096 + oh*64 + ow0;
    int cg = t & 31, ng = t >> 5;
    float pacc[4][5];
    #pragma unroll
    for (int nn = 0; nn < 4; nn++)
        #pragma unroll
        for (int m = 0; m < 5; m++) pacc[nn][m] = 0.f;
    for (int k = 0; k < 64; k++) {
        float w0 = buf[k*136 + cg];
        float w1 = buf[k*136 + cg + 32];
        float w2 = buf[k*136 + cg + 64];
        float w3 = buf[k*136 + cg + 96];
        float w4 = (cg < 4) ? buf[k*136 + 128 + cg] : 0.f;
        #pragma unroll
        for (int nn = 0; nn < 4; nn++) {
            float yv = ys[(ng*4 + nn)*68 + k];
            pacc[nn][0] += yv*w0; pacc[nn][1] += yv*w1;
            pacc[nn][2] += yv*w2; pacc[nn][3] += yv*w3;
            pacc[nn][4] += yv*w4;
        }
    }
    #pragma unroll
    for (int nn = 0; nn < 4; nn++) {
        int node = i0 + ng*4 + nn;
        g_h0[node*64 + cg]      = pacc[nn][0];
        g_h0[node*64 + cg + 32] = pacc[nn][1];
        g_h1[node*64 + cg]      = pacc[nn][2];
        g_h1[node*64 + cg + 32] = pacc[nn][3];
        if (cg == 0) g_f10[node] = pacc[nn][4];
        else if (cg == 1) g_f20[node] = pacc[nn][4];
        else if (cg == 2) g_f11[node] = pacc[nn][4];
        else if (cg == 3) g_f21[node] = pacc[nn][4];
    }
}

// ---------------- dummy (positions knn at profile index 3) ----------------
__global__ void dummy_kernel() {}

// ---------------- K3: kNN partials — register i-row, JSPLIT 16, 6 blocks/SM ----------------
__global__ void __launch_bounds__(128, 6) knn_part_kernel() {
    __shared__ __align__(16) float yj[JT*64];   // 32KB, broadcast-only access
    __shared__ float sqj[JT];
    int t = threadIdx.x;                        // 128
    int ic = blockIdx.x >> 4;                   // 64 i-chunks of 128 rows
    int js = blockIdx.x & 15;
    int i0 = ic * 128;
    int i = i0 + t;
    int jsbase = js * JRANGE;
    int jbase = (i0 & ~4095) + jsbase;

    ulonglong2 yiv[16];
    #pragma unroll
    for (int c4 = 0; c4 < 16; c4++)
        yiv[c4] = *(const ulonglong2*)&g_y[i*64 + c4*4];
    float si = g_sq[i];

    ull ktop[7];
    const ull SENT = ((ull)0x7F7FFFFFull << 32) | 0x7FFFFFFFull;
    #pragma unroll
    for (int s = 0; s < 7; s++) ktop[s] = SENT;
    float bd6 = 3.4028235e38f;

    for (int jt0 = 0; jt0 < JRANGE; jt0 += JT) {
        __syncthreads();
        for (int idx = t; idx < JT*16; idx += 128) {
            int row = idx >> 4, c4 = idx & 15;
            *(float4*)&yj[row*64 + c4*4] = *(const float4*)&g_y[(jbase + jt0 + row)*64 + c4*4];
        }
        if (t < JT) sqj[t] = g_sq[jbase + jt0 + t];
        __syncthreads();

        for (int jl = 0; jl < JT; jl += 2) {
            const ulonglong2* p0 = (const ulonglong2*)&yj[jl*64];
            const ulonglong2* p1 = (const ulonglong2*)&yj[(jl+1)*64];
            ull a0e = 0, a0o = 0, a1e = 0, a1o = 0;
            #pragma unroll
            for (int c2 = 0; c2 < 16; c2++) {
                ulonglong2 u0 = p0[c2];
                ulonglong2 u1 = p1[c2];
                a0e = fma2(yiv[c2].x, u0.x, a0e);
                a0o = fma2(yiv[c2].y, u0.y, a0o);
                a1e = fma2(yiv[c2].x, u1.x, a1e);
                a1o = fma2(yiv[c2].y, u1.y, a1o);
            }
            float d0 = si + sqj[jl]   - 2.f*(sum2(a0e) + sum2(a0o));
            float d1 = si + sqj[jl+1] - 2.f*(sum2(a1e) + sum2(a1o));
            d0 = fmaxf(d0, 0.f);
            d1 = fmaxf(d1, 0.f);
            int j0 = jsbase + jt0 + jl;   // j within batch, ascending scan
            // ascending-j + strict-less float gate == stable tie-break
            if (d0 < bd6) {
                ull key = ((ull)__float_as_uint(d0) << 32) | (unsigned)j0;
                ktop[6] = key;
                #pragma unroll
                for (int s = 5; s >= 0; s--)
                    if (ktop[s+1] < ktop[s]) { ull tm = ktop[s]; ktop[s] = ktop[s+1]; ktop[s+1] = tm; }
                bd6 = __uint_as_float((unsigned)(ktop[6] >> 32));
            }
            if (d1 < bd6) {
                ull key = ((ull)__float_as_uint(d1) << 32) | (unsigned)(j0 + 1);
                ktop[6] = key;
                #pragma unroll
                for (int s = 5; s >= 0; s--)
                    if (ktop[s+1] < ktop[s]) { ull tm = ktop[s]; ktop[s] = ktop[s+1]; ktop[s+1] = tm; }
                bd6 = __uint_as_float((unsigned)(ktop[6] >> 32));
            }
        }
    }
    #pragma unroll
    for (int s = 0; s < 7; s++)
        g_part[(i*JSPLIT + js)*7 + s] = ktop[s];
}

// ---------------- K5: fused merge + attention agg heads 0/1 + out-head projection ----------------
__global__ void gat_mid_kernel(const float* __restrict__ W_out) {
    __shared__ float Wo[128*72];     // 36,864 B
    __shared__ float hs[16*136];     //  8,704 B
    __shared__ int   snbr[16][7];
    __shared__ float satt[16][2][7];
    int t = threadIdx.x;             // 256
    int i0 = blockIdx.x * 16;
    int bb = i0 & ~4095;

    if (t < 16) {
        int node = i0 + t;
        ull best[7];
        #pragma unroll
        for (int s = 0; s < 7; s++) best[s] = 0xFFFFFFFFFFFFFFFFull;
        for (int js = 0; js < JSPLIT; js++) {
            const ull* pp = &g_part[(node*JSPLIT + js)*7];
            #pragma unroll
            for (int s = 0; s < 7; s++) {
                ull k = pp[s];
                if (k < best[6]) {
                    best[6] = k;
                    #pragma unroll
                    for (int q = 5; q >= 0; q--)
                        if (best[q+1] < best[q]) { ull tm = best[q]; best[q] = best[q+1]; best[q+1] = tm; }
                }
            }
        }
        #pragma unroll
        for (int s = 0; s < 7; s++) {
            int j = (int)(unsigned)(best[s] & 0xffffffffull);
            snbr[t][s] = j;
            g_nbr[node*7 + s] = j;
        }
    }
    for (int idx = t; idx < 128*72; idx += 256) {
        int k = idx / 72, c = idx % 72;
        float v = 0.f;
        if (c < 64) v = W_out[k*64 + c];
        else if (c == 64) v = g_vaO[k];
        else if (c == 65) v = g_vaO[128 + k];
        Wo[idx] = v;
    }
    __syncthreads();

    if (t < 32) {
        int n = t >> 1, head = t & 1;
        int node = i0 + n;
        const float* f1 = head ? g_f11 : g_f10;
        const float* f2 = head ? g_f21 : g_f20;
        float fi = f1[node];
        float e[7], m = -3.4e38f;
        #pragma unroll
        for (int s = 0; s < 7; s++) {
            float v = fi + f2[bb + snbr[n][s]];
            v = v > 0.f ? v : 0.2f*v;
            e[s] = v; if (v > m) m = v;
        }
        float sum = 0.f;
        #pragma unroll
        for (int s = 0; s < 7; s++) { e[s] = expf(e[s] - m); sum += e[s]; }
        float inv = 1.f / sum;
        #pragma unroll
        for (int s = 0; s < 7; s++) satt[n][head][s] = e[s]*inv;
    }
    __syncthreads();

    for (int idx = t; idx < 2048; idx += 256) {
        int n = idx >> 7, q = idx & 127;
        int head = q >> 6, c = q & 63;
        const float* h = head ? g_h1 : g_h0;
        float acc = 0.f;
        #pragma unroll
        for (int s = 0; s < 7; s++)
            acc += satt[n][head][s] * h[(bb + snbr[n][s])*64 + c];
        acc = acc > 0.f ? acc : 0.f;
        hs[n*136 + q] = acc;
    }
    __syncthreads();

    int cg = t & 31, ng = t >> 5;
    float acc[2][3];
    #pragma unroll
    for (int nn = 0; nn < 2; nn++)
        #pragma unroll
        for (int m = 0; m < 3; m++) acc[nn][m] = 0.f;
    for (int k = 0; k < 128; k++) {
        float w0 = Wo[k*72 + cg];
        float w1 = Wo[k*72 + cg + 32];
        float w2 = (cg < 2) ? Wo[k*72 + 64 + cg] : 0.f;
        #pragma unroll
        for (int nn = 0; nn < 2; nn++) {
            float yv = hs[(ng*2 + nn)*136 + k];
            acc[nn][0] += yv*w0; acc[nn][1] += yv*w1; acc[nn][2] += yv*w2;
        }
    }
    #pragma unroll
    for (int nn = 0; nn < 2; nn++) {
        int node = i0 + ng*2 + nn;
        g_ho[node*64 + cg]      = acc[nn][0];
        g_ho[node*64 + cg + 32] = acc[nn][1];
        if (cg == 0) g_f1o[node] = acc[nn][2];
        else if (cg == 1) g_f2o[node] = acc[nn][2];
    }
}

// ---------------- K7: out-head agg + elu + log_softmax ----------------
__global__ void aggout_kernel() {
    __shared__ float wmax[4][2];
    __shared__ float wsum[4][2];
    int t = threadIdx.x;
    int ln = t >> 6, c = t & 63;
    int node = blockIdx.x*4 + ln;
    int lane = t & 31, wh = (t >> 5) & 1;
    int bb = node & ~4095;
    int nb[7];
    #pragma unroll
    for (int s = 0; s < 7; s++) nb[s] = bb + g_nbr[node*7 + s];
    float fi = g_f1o[node];
    float e[7], m = -3.4e38f;
    #pragma unroll
    for (int s = 0; s < 7; s++) {
        float v = fi + g_f2o[nb[s]];
        v = v > 0.f ? v : 0.2f*v;
        e[s] = v; if (v > m) m = v;
    }
    float sum = 0.f;
    #pragma unroll
    for (int s = 0; s < 7; s++) { e[s] = expf(e[s] - m); sum += e[s]; }
    float inv = 1.f / sum;
    float acc = 0.f;
    #pragma unroll
    for (int s = 0; s < 7; s++) acc += e[s]*inv * g_ho[nb[s]*64 + c];
    float v = acc > 0.f ? acc : (expf(acc) - 1.f);

    float mx = v;
    #pragma unroll
    for (int off = 16; off; off >>= 1) mx = fmaxf(mx, __shfl_down_sync(0xffffffffu, mx, off));
    if (lane == 0) wmax[ln][wh] = mx;
    __syncthreads();
    mx = fmaxf(wmax[ln][0], wmax[ln][1]);
    float p = expf(v - mx);
    float ssum = p;
    #pragma unroll
    for (int off = 16; off; off >>= 1) ssum += __shfl_down_sync(0xffffffffu, ssum, off);
    if (lane == 0) wsum[ln][wh] = ssum;
    __syncthreads();
    float tot = wsum[ln][0] + wsum[ln][1];
    g_outn[node*64 + c] = v - mx - logf(tot);
}

// ---------------- K8: ConvTranspose2d (f32x2-packed register tiling) ----------------
__global__ void convt_kernel(const float* __restrict__ b_last, float* __restrict__ out) {
    int b = blockIdx.x >> 7;
    int oh = blockIdx.x & 127;
    __shared__ __align__(16) float sin[2][64*68];
    int khs[2], ihs[2];
    int cnt = 0;
    for (int kh = 0; kh < 3; kh++) {
        int num = oh + 1 - kh;
        if (num & 1) continue;
        int ih = num >> 1;
        if (ih < 0 || ih >= 64) continue;
        khs[cnt] = kh; ihs[cnt] = ih; cnt++;
    }
    int t = threadIdx.x;
    for (int r = 0; r < cnt; r++) {
        const float* src = &g_outn[((b << 12) + ihs[r]*64)*64];
        for (int idx = t; idx < 1024; idx += 256) {
            int iw = idx >> 4, c4 = idx & 15;
            *(float4*)&sin[r][iw*68 + c4*4] = *(const float4*)&src[iw*64 + c4*4];
        }
    }
    __syncthreads();
    int cog = t & 15, owg = t >> 4;
    ull accP[8][2];
    #pragma unroll
    for (int q = 0; q < 8; q++) { accP[q][0] = 0ull; accP[q][1] = 0ull; }

    for (int r = 0; r < cnt; r++) {
        int kh = khs[r];
        #pragma unroll
        for (int kw = 0; kw < 3; kw++) {
            int iwq[4]; bool vq[4];
            #pragma unroll
            for (int u = 0; u < 4; u++) {
                int q = ((kw + 1) & 1) + 2*u;
                int num = owg*8 + q + 1 - kw;
                int iw = num >> 1;
                iwq[u] = iw;
                vq[u] = (num >= 0) && (iw < 64);
            }
            const float* wbase = &g_wt[(kh*3 + kw)*4096 + cog*4];
            for (int ci0 = 0; ci0 < 64; ci0 += 4) {
                ulonglong2 w0 = *(const ulonglong2*)&wbase[(ci0+0)*64];
                ulonglong2 w1 = *(const ulonglong2*)&wbase[(ci0+1)*64];
                ulonglong2 w2 = *(const ulonglong2*)&wbase[(ci0+2)*64];
                ulonglong2 w3 = *(const ulonglong2*)&wbase[(ci0+3)*64];
                #pragma unroll
                for (int u = 0; u < 4; u++) {
                    if (!vq[u]) continue;
                    int q = ((kw + 1) & 1) + 2*u;
                    float4 iv = *(const float4*)&sin[r][iwq[u]*68 + ci0];
                    ull dx = dup2(iv.x), dy = dup2(iv.y), dz = dup2(iv.z), dw = dup2(iv.w);
                    accP[q][0] = fma2(dx, w0.x, accP[q][0]);
                    accP[q][1] = fma2(dx, w0.y, accP[q][1]);
                    accP[q][0] = fma2(dy, w1.x, accP[q][0]);
                    accP[q][1] = fma2(dy, w1.y, accP[q][1]);
                    accP[q][0] = fma2(dz, w2.x, accP[q][0]);
                    accP[q][1] = fma2(dz, w2.y, accP[q][1]);
                    accP[q][0] = fma2(dw, w3.x, accP[q][0]);
                    accP[q][1] = fma2(dw, w3.y, accP[q][1]);
                }
            }
        }
    }
    #pragma unroll
    for (int cc = 0; cc < 4; cc++) {
        int co = cog*4 + cc;
        float bv = b_last[co];
        int pair = cc >> 1;
        bool high = cc & 1;
        float4 o0, o1;
        o0.x = (high ? hi2(accP[0][pair]) : lo2(accP[0][pair])) + bv;
        o0.y = (high ? hi2(accP[1][pair]) : lo2(accP[1][pair])) + bv;
        o0.z = (high ? hi2(accP[2][pair]) : lo2(accP[2][pair])) + bv;
        o0.w = (high ? hi2(accP[3][pair]) : lo2(accP[3][pair])) + bv;
        o1.x = (high ? hi2(accP[4][pair]) : lo2(accP[4][pair])) + bv;
        o1.y = (high ? hi2(accP[5][pair]) : lo2(accP[5][pair])) + bv;
        o1.z = (high ? hi2(accP[6][pair]) : lo2(accP[6][pair])) + bv;
        o1.w = (high ? hi2(accP[7][pair]) : lo2(accP[7][pair])) + bv;
        float* dst = &out[((b*64 + co)*128 + oh)*128 + owg*8];
        *(float4*)&dst[0] = o0;
        *(float4*)&dst[4] = o1;
    }
}

// ---------------- launcher ----------------
extern "C" void kernel_launch(void* const* d_in, const int* in_sizes, int n_in,
                              void* d_out, int out_size) {
    const float* x      = (const float*)d_in[0];
    const float* w_head = (const float*)d_in[1];
    const float* b_head = (const float*)d_in[2];
    const float* W0     = (const float*)d_in[3];
    const float* a0     = (const float*)d_in[4];
    const float* W1     = (const float*)d_in[5];
    const float* a1     = (const float*)d_in[6];
    const float* W_out  = (const float*)d_in[7];
    const float* a_out  = (const float*)d_in[8];
    const float* w_last = (const float*)d_in[9];
    const float* b_last = (const float*)d_in[10];
    float* out = (float*)d_out;

    prep_kernel<<<216, 256>>>(w_last, w_head, W0, a0, W1, a1, W_out, a_out);  // 0
    conv_proj_kernel<<<256, 256>>>(x, b_head, W0, W1);                        // 1
    dummy_kernel<<<1, 32>>>();                                                // 2
    knn_part_kernel<<<(NTOT/128)*JSPLIT, 128>>>();                            // 3 (profiled)
    gat_mid_kernel<<<NTOT/16, 256>>>(W_out);                                  // 4
    aggout_kernel<<<NTOT/4, 256>>>();                                         // 5
    convt_kernel<<<NB*128, 256>>>(b_last, out);                               // 6
}

// round 16
// speedup vs baseline: 1.6782x; 1.6782x over previous
#include <cuda_runtime.h>
#include <cuda_bf16.h>

typedef unsigned long long ull;

#define NB 2
#define NPB 4096
#define NTOT (NB*NPB)
#define JSPLIT 16
#define JRANGE (NPB/JSPLIT)   // 256
#define JT 128                // j rows staged in smem per step

// ---------------- scratch ----------------
__device__ float g_y[NTOT*64];
__device__ float g_sq[NTOT];
__device__ int   g_nbr[NTOT*7];
__device__ ull   g_part[NTOT*JSPLIT*7];   // partial top-7 keys
__device__ float g_h0[NTOT*64], g_h1[NTOT*64];
__device__ float g_f10[NTOT], g_f20[NTOT], g_f11[NTOT], g_f21[NTOT];
__device__ float g_ho[NTOT*64];
__device__ float g_f1o[NTOT], g_f2o[NTOT];
__device__ float g_outn[NTOT*64];
__device__ float g_wt[9*64*64];      // convT weights [k][ci][co]
__device__ float g_wc[31*9*64];      // conv-head weights [ci*9+k][co]
__device__ float g_va[4*64];         // folded attention vecs heads 0/1
__device__ float g_vaO[2*128];       // folded attention vecs out head

__device__ __forceinline__ ull fma2(ull a, ull b, ull c) {
    ull d;
    asm("fma.rn.f32x2 %0, %1, %2, %3;" : "=l"(d) : "l"(a), "l"(b), "l"(c));
    return d;
}
__device__ __forceinline__ float sum2(ull v) {
    return __uint_as_float((unsigned)(v & 0xffffffffull))
         + __uint_as_float((unsigned)(v >> 32));
}
__device__ __forceinline__ ull dup2(float v) {
    ull r;
    asm("mov.b64 %0, {%1, %1};" : "=l"(r) : "r"(__float_as_uint(v)));
    return r;
}
__device__ __forceinline__ float lo2(ull v) { return __uint_as_float((unsigned)(v & 0xffffffffull)); }
__device__ __forceinline__ float hi2(ull v) { return __uint_as_float((unsigned)(v >> 32)); }

// ---------------- K0: prep (repacks + folded attention vectors) ----------------
__global__ void prep_kernel(const float* __restrict__ w_last,
                            const float* __restrict__ w_head,
                            const float* __restrict__ W0, const float* __restrict__ a0,
                            const float* __restrict__ W1, const float* __restrict__ a1,
                            const float* __restrict__ W_out, const float* __restrict__ a_out) {
    int idx = blockIdx.x * 256 + threadIdx.x;
    if (idx < 36864) {
        int co = idx & 63, ci = (idx >> 6) & 63, k = idx >> 12;
        g_wt[(k*64 + ci)*64 + co] = w_last[(ci*64 + co)*9 + k];
    } else if (idx < 36864 + 17856) {
        int j = idx - 36864;          // j = (ci*9+k)*64+co
        int co = j & 63, rest = j >> 6;
        int k = rest % 9, ci = rest / 9;
        g_wc[j] = w_head[(co*31 + ci)*9 + k];
    } else if (idx < 36864 + 17856 + 256) {
        int j = idx - 54720;
        int head = j >> 7, which = (j >> 6) & 1, k = j & 63;
        const float* W = head ? W1 : W0;
        const float* a = head ? a1 : a0;
        float s = 0.f;
        for (int c = 0; c < 64; c++) s += W[k*64 + c] * a[which*64 + c];
        g_va[(head*2 + which)*64 + k] = s;
    } else if (idx < 36864 + 17856 + 512) {
        int j = idx - 54976;
        int which = j >> 7, k = j & 127;
        float s = 0.f;
        for (int c = 0; c < 64; c++) s += W_out[k*64 + c] * a_out[which*64 + c];
        g_vaO[which*128 + k] = s;
    }
}

// ---------------- K1: fused conv head + squared norms + proj heads 0/1 ----------------
__global__ void conv_proj_kernel(const float* __restrict__ x,
                                 const float* __restrict__ bias,
                                 const float* __restrict__ W0,
                                 const float* __restrict__ W1) {
    __shared__ float ys[32*68];       // 8,704 B  (y slab, node-major)
    __shared__ float buf[64*136];     // 34,816 B (union: sIn / Wc)
    int blk = blockIdx.x;             // b(1) | oh(6) | half(1)
    int b = blk >> 7;
    int oh = (blk >> 1) & 63;
    int half = blk & 1;
    int ow0 = half * 32;
    int t = threadIdx.x;              // 256

    for (int idx = t; idx < 31*3*66; idx += 256) {
        int iwp = idx % 66;
        int rem = idx / 66;
        int r = rem % 3, ci = rem / 3;
        int ih = oh*2 - 1 + r, iw = ow0*2 - 1 + iwp;
        float v = 0.f;
        if ((unsigned)ih < 128u && (unsigned)iw < 128u)
            v = x[((b*31 + ci)*128 + ih)*128 + iw];
        buf[idx] = v;
    }
    __syncthreads();

    // conv phase, f32x2-packed accumulators
    int cog = t & 15, owg = t >> 4;
    ull accP[2][2];
    #pragma unroll
    for (int q = 0; q < 2; q++) { accP[q][0] = 0ull; accP[q][1] = 0ull; }
    for (int ci = 0; ci < 31; ci++) {
        #pragma unroll
        for (int r = 0; r < 3; r++) {
            int ib = (ci*3 + r)*66 + owg*4;
            #pragma unroll
            for (int kw = 0; kw < 3; kw++) {
                ulonglong2 wv = *(const ulonglong2*)&g_wc[((ci*9 + r*3 + kw)*64) + cog*4];
                #pragma unroll
                for (int q = 0; q < 2; q++) {
                    ull iv = dup2(buf[ib + 2*q + kw]);
                    accP[q][0] = fma2(iv, wv.x, accP[q][0]);
                    accP[q][1] = fma2(iv, wv.y, accP[q][1]);
                }
            }
        }
    }
    float4 bv = *(const float4*)&bias[cog*4];
    float ssq[2];
    #pragma unroll
    for (int q = 0; q < 2; q++) {
        int node = b*4096 + oh*64 + ow0 + owg*2 + q;
        float4 o;
        o.x = lo2(accP[q][0]) + bv.x; o.y = hi2(accP[q][0]) + bv.y;
        o.z = lo2(accP[q][1]) + bv.z; o.w = hi2(accP[q][1]) + bv.w;
        *(float4*)&g_y[node*64 + cog*4] = o;
        *(float4*)&ys[(owg*2 + q)*68 + cog*4] = o;
        ssq[q] = o.x*o.x + o.y*o.y + o.z*o.z + o.w*o.w;
    }
    #pragma unroll
    for (int off = 1; off <= 8; off <<= 1)
        #pragma unroll
        for (int q = 0; q < 2; q++)
            ssq[q] += __shfl_xor_sync(0xffffffffu, ssq[q], off);
    if (cog == 0) {
        #pragma unroll
        for (int q = 0; q < 2; q++)
            g_sq[b*4096 + oh*64 + ow0 + owg*2 + q] = ssq[q];
    }
    __syncthreads();

    for (int idx = t; idx < 64*136; idx += 256) {
        int k = idx / 136, c = idx % 136;
        float v = 0.f;
        if (c < 64) v = W0[k*64 + c];
        else if (c < 128) v = W1[k*64 + c - 64];
        else if (c < 132) v = g_va[(c - 128)*64 + k];
        buf[idx] = v;
    }
    __syncthreads();

    int i0 = b*4096 + oh*64 + ow0;
    int cg = t & 31, ng = t >> 5;
    float pacc[4][5];
    #pragma unroll
    for (int nn = 0; nn < 4; nn++)
        #pragma unroll
        for (int m = 0; m < 5; m++) pacc[nn][m] = 0.f;
    for (int k = 0; k < 64; k++) {
        float w0 = buf[k*136 + cg];
        float w1 = buf[k*136 + cg + 32];
        float w2 = buf[k*136 + cg + 64];
        float w3 = buf[k*136 + cg + 96];
        float w4 = (cg < 4) ? buf[k*136 + 128 + cg] : 0.f;
        #pragma unroll
        for (int nn = 0; nn < 4; nn++) {
            float yv = ys[(ng*4 + nn)*68 + k];
            pacc[nn][0] += yv*w0; pacc[nn][1] += yv*w1;
            pacc[nn][2] += yv*w2; pacc[nn][3] += yv*w3;
            pacc[nn][4] += yv*w4;
        }
    }
    #pragma unroll
    for (int nn = 0; nn < 4; nn++) {
        int node = i0 + ng*4 + nn;
        g_h0[node*64 + cg]      = pacc[nn][0];
        g_h0[node*64 + cg + 32] = pacc[nn][1];
        g_h1[node*64 + cg]      = pacc[nn][2];
        g_h1[node*64 + cg + 32] = pacc[nn][3];
        if (cg == 0) g_f10[node] = pacc[nn][4];
        else if (cg == 1) g_f20[node] = pacc[nn][4];
        else if (cg == 2) g_f11[node] = pacc[nn][4];
        else if (cg == 3) g_f21[node] = pacc[nn][4];
    }
}

// ---------------- dummy (positions knn at profile index 3) ----------------
__global__ void dummy_kernel() {}

// ---------------- K3: kNN partials — register i-row, JSPLIT 16, NO reg cap ----------------
__global__ void __launch_bounds__(128, 4) knn_part_kernel() {
    __shared__ __align__(16) float yj[JT*64];   // 32KB, broadcast-only access
    __shared__ float sqj[JT];
    int t = threadIdx.x;                        // 128
    int ic = blockIdx.x >> 4;                   // 64 i-chunks of 128 rows
    int js = blockIdx.x & 15;
    int i0 = ic * 128;
    int i = i0 + t;
    int jsbase = js * JRANGE;
    int jbase = (i0 & ~4095) + jsbase;

    ulonglong2 yiv[16];
    #pragma unroll
    for (int c4 = 0; c4 < 16; c4++)
        yiv[c4] = *(const ulonglong2*)&g_y[i*64 + c4*4];
    float si = g_sq[i];

    ull ktop[7];
    const ull SENT = ((ull)0x7F7FFFFFull << 32) | 0x7FFFFFFFull;
    #pragma unroll
    for (int s = 0; s < 7; s++) ktop[s] = SENT;
    float bd6 = 3.4028235e38f;

    for (int jt0 = 0; jt0 < JRANGE; jt0 += JT) {
        __syncthreads();
        for (int idx = t; idx < JT*16; idx += 128) {
            int row = idx >> 4, c4 = idx & 15;
            *(float4*)&yj[row*64 + c4*4] = *(const float4*)&g_y[(jbase + jt0 + row)*64 + c4*4];
        }
        if (t < JT) sqj[t] = g_sq[jbase + jt0 + t];
        __syncthreads();

        for (int jl = 0; jl < JT; jl += 2) {
            const ulonglong2* p0 = (const ulonglong2*)&yj[jl*64];
            const ulonglong2* p1 = (const ulonglong2*)&yj[(jl+1)*64];
            ull a0e = 0, a0o = 0, a1e = 0, a1o = 0;
            #pragma unroll
            for (int c2 = 0; c2 < 16; c2++) {
                ulonglong2 u0 = p0[c2];
                ulonglong2 u1 = p1[c2];
                a0e = fma2(yiv[c2].x, u0.x, a0e);
                a0o = fma2(yiv[c2].y, u0.y, a0o);
                a1e = fma2(yiv[c2].x, u1.x, a1e);
                a1o = fma2(yiv[c2].y, u1.y, a1o);
            }
            float d0 = si + sqj[jl]   - 2.f*(sum2(a0e) + sum2(a0o));
            float d1 = si + sqj[jl+1] - 2.f*(sum2(a1e) + sum2(a1o));
            d0 = fmaxf(d0, 0.f);
            d1 = fmaxf(d1, 0.f);
            int j0 = jsbase + jt0 + jl;   // j within batch, ascending scan
            // ascending-j + strict-less float gate == stable tie-break
            if (d0 < bd6) {
                ull key = ((ull)__float_as_uint(d0) << 32) | (unsigned)j0;
                ktop[6] = key;
                #pragma unroll
                for (int s = 5; s >= 0; s--)
                    if (ktop[s+1] < ktop[s]) { ull tm = ktop[s]; ktop[s] = ktop[s+1]; ktop[s+1] = tm; }
                bd6 = __uint_as_float((unsigned)(ktop[6] >> 32));
            }
            if (d1 < bd6) {
                ull key = ((ull)__float_as_uint(d1) << 32) | (unsigned)(j0 + 1);
                ktop[6] = key;
                #pragma unroll
                for (int s = 5; s >= 0; s--)
                    if (ktop[s+1] < ktop[s]) { ull tm = ktop[s]; ktop[s] = ktop[s+1]; ktop[s+1] = tm; }
                bd6 = __uint_as_float((unsigned)(ktop[6] >> 32));
            }
        }
    }
    #pragma unroll
    for (int s = 0; s < 7; s++)
        g_part[(i*JSPLIT + js)*7 + s] = ktop[s];
}

// ---------------- K5: fused merge + attention agg heads 0/1 + out-head projection ----------------
__global__ void gat_mid_kernel(const float* __restrict__ W_out) {
    __shared__ float Wo[128*72];     // 36,864 B
    __shared__ float hs[16*136];     //  8,704 B
    __shared__ int   snbr[16][7];
    __shared__ float satt[16][2][7];
    int t = threadIdx.x;             // 256
    int i0 = blockIdx.x * 16;
    int bb = i0 & ~4095;

    if (t < 16) {
        int node = i0 + t;
        ull best[7];
        #pragma unroll
        for (int s = 0; s < 7; s++) best[s] = 0xFFFFFFFFFFFFFFFFull;
        for (int js = 0; js < JSPLIT; js++) {
            const ull* pp = &g_part[(node*JSPLIT + js)*7];
            #pragma unroll
            for (int s = 0; s < 7; s++) {
                ull k = pp[s];
                if (k < best[6]) {
                    best[6] = k;
                    #pragma unroll
                    for (int q = 5; q >= 0; q--)
                        if (best[q+1] < best[q]) { ull tm = best[q]; best[q] = best[q+1]; best[q+1] = tm; }
                }
            }
        }
        #pragma unroll
        for (int s = 0; s < 7; s++) {
            int j = (int)(unsigned)(best[s] & 0xffffffffull);
            snbr[t][s] = j;
            g_nbr[node*7 + s] = j;
        }
    }
    for (int idx = t; idx < 128*72; idx += 256) {
        int k = idx / 72, c = idx % 72;
        float v = 0.f;
        if (c < 64) v = W_out[k*64 + c];
        else if (c == 64) v = g_vaO[k];
        else if (c == 65) v = g_vaO[128 + k];
        Wo[idx] = v;
    }
    __syncthreads();

    if (t < 32) {
        int n = t >> 1, head = t & 1;
        int node = i0 + n;
        const float* f1 = head ? g_f11 : g_f10;
        const float* f2 = head ? g_f21 : g_f20;
        float fi = f1[node];
        float e[7], m = -3.4e38f;
        #pragma unroll
        for (int s = 0; s < 7; s++) {
            float v = fi + f2[bb + snbr[n][s]];
            v = v > 0.f ? v : 0.2f*v;
            e[s] = v; if (v > m) m = v;
        }
        float sum = 0.f;
        #pragma unroll
        for (int s = 0; s < 7; s++) { e[s] = expf(e[s] - m); sum += e[s]; }
        float inv = 1.f / sum;
        #pragma unroll
        for (int s = 0; s < 7; s++) satt[n][head][s] = e[s]*inv;
    }
    __syncthreads();

    for (int idx = t; idx < 2048; idx += 256) {
        int n = idx >> 7, q = idx & 127;
        int head = q >> 6, c = q & 63;
        const float* h = head ? g_h1 : g_h0;
        float acc = 0.f;
        #pragma unroll
        for (int s = 0; s < 7; s++)
            acc += satt[n][head][s] * h[(bb + snbr[n][s])*64 + c];
        acc = acc > 0.f ? acc : 0.f;
        hs[n*136 + q] = acc;
    }
    __syncthreads();

    int cg = t & 31, ng = t >> 5;
    float acc[2][3];
    #pragma unroll
    for (int nn = 0; nn < 2; nn++)
        #pragma unroll
        for (int m = 0; m < 3; m++) acc[nn][m] = 0.f;
    for (int k = 0; k < 128; k++) {
        float w0 = Wo[k*72 + cg];
        float w1 = Wo[k*72 + cg + 32];
        float w2 = (cg < 2) ? Wo[k*72 + 64 + cg] : 0.f;
        #pragma unroll
        for (int nn = 0; nn < 2; nn++) {
            float yv = hs[(ng*2 + nn)*136 + k];
            acc[nn][0] += yv*w0; acc[nn][1] += yv*w1; acc[nn][2] += yv*w2;
        }
    }
    #pragma unroll
    for (int nn = 0; nn < 2; nn++) {
        int node = i0 + ng*2 + nn;
        g_ho[node*64 + cg]      = acc[nn][0];
        g_ho[node*64 + cg + 32] = acc[nn][1];
        if (cg == 0) g_f1o[node] = acc[nn][2];
        else if (cg == 1) g_f2o[node] = acc[nn][2];
    }
}

// ---------------- K7: out-head agg + elu + log_softmax ----------------
__global__ void aggout_kernel() {
    __shared__ float wmax[4][2];
    __shared__ float wsum[4][2];
    int t = threadIdx.x;
    int ln = t >> 6, c = t & 63;
    int node = blockIdx.x*4 + ln;
    int lane = t & 31, wh = (t >> 5) & 1;
    int bb = node & ~4095;
    int nb[7];
    #pragma unroll
    for (int s = 0; s < 7; s++) nb[s] = bb + g_nbr[node*7 + s];
    float fi = g_f1o[node];
    float e[7], m = -3.4e38f;
    #pragma unroll
    for (int s = 0; s < 7; s++) {
        float v = fi + g_f2o[nb[s]];
        v = v > 0.f ? v : 0.2f*v;
        e[s] = v; if (v > m) m = v;
    }
    float sum = 0.f;
    #pragma unroll
    for (int s = 0; s < 7; s++) { e[s] = expf(e[s] - m); sum += e[s]; }
    float inv = 1.f / sum;
    float acc = 0.f;
    #pragma unroll
    for (int s = 0; s < 7; s++) acc += e[s]*inv * g_ho[nb[s]*64 + c];
    float v = acc > 0.f ? acc : (expf(acc) - 1.f);

    float mx = v;
    #pragma unroll
    for (int off = 16; off; off >>= 1) mx = fmaxf(mx, __shfl_down_sync(0xffffffffu, mx, off));
    if (lane == 0) wmax[ln][wh] = mx;
    __syncthreads();
    mx = fmaxf(wmax[ln][0], wmax[ln][1]);
    float p = expf(v - mx);
    float ssum = p;
    #pragma unroll
    for (int off = 16; off; off >>= 1) ssum += __shfl_down_sync(0xffffffffu, ssum, off);
    if (lane == 0) wsum[ln][wh] = ssum;
    __syncthreads();
    float tot = wsum[ln][0] + wsum[ln][1];
    g_outn[node*64 + c] = v - mx - logf(tot);
}

// ---------------- K8: ConvTranspose2d (f32x2-packed register tiling) ----------------
__global__ void convt_kernel(const float* __restrict__ b_last, float* __restrict__ out) {
    int b = blockIdx.x >> 7;
    int oh = blockIdx.x & 127;
    __shared__ __align__(16) float sin[2][64*68];
    int khs[2], ihs[2];
    int cnt = 0;
    for (int kh = 0; kh < 3; kh++) {
        int num = oh + 1 - kh;
        if (num & 1) continue;
        int ih = num >> 1;
        if (ih < 0 || ih >= 64) continue;
        khs[cnt] = kh; ihs[cnt] = ih; cnt++;
    }
    int t = threadIdx.x;
    for (int r = 0; r < cnt; r++) {
        const float* src = &g_outn[((b << 12) + ihs[r]*64)*64];
        for (int idx = t; idx < 1024; idx += 256) {
            int iw = idx >> 4, c4 = idx & 15;
            *(float4*)&sin[r][iw*68 + c4*4] = *(const float4*)&src[iw*64 + c4*4];
        }
    }
    __syncthreads();
    int cog = t & 15, owg = t >> 4;
    ull accP[8][2];
    #pragma unroll
    for (int q = 0; q < 8; q++) { accP[q][0] = 0ull; accP[q][1] = 0ull; }

    for (int r = 0; r < cnt; r++) {
        int kh = khs[r];
        #pragma unroll
        for (int kw = 0; kw < 3; kw++) {
            int iwq[4]; bool vq[4];
            #pragma unroll
            for (int u = 0; u < 4; u++) {
                int q = ((kw + 1) & 1) + 2*u;
                int num = owg*8 + q + 1 - kw;
                int iw = num >> 1;
                iwq[u] = iw;
                vq[u] = (num >= 0) && (iw < 64);
            }
            const float* wbase = &g_wt[(kh*3 + kw)*4096 + cog*4];
            for (int ci0 = 0; ci0 < 64; ci0 += 4) {
                ulonglong2 w0 = *(const ulonglong2*)&wbase[(ci0+0)*64];
                ulonglong2 w1 = *(const ulonglong2*)&wbase[(ci0+1)*64];
                ulonglong2 w2 = *(const ulonglong2*)&wbase[(ci0+2)*64];
                ulonglong2 w3 = *(const ulonglong2*)&wbase[(ci0+3)*64];
                #pragma unroll
                for (int u = 0; u < 4; u++) {
                    if (!vq[u]) continue;
                    int q = ((kw + 1) & 1) + 2*u;
                    float4 iv = *(const float4*)&sin[r][iwq[u]*68 + ci0];
                    ull dx = dup2(iv.x), dy = dup2(iv.y), dz = dup2(iv.z), dw = dup2(iv.w);
                    accP[q][0] = fma2(dx, w0.x, accP[q][0]);
                    accP[q][1] = fma2(dx, w0.y, accP[q][1]);
                    accP[q][0] = fma2(dy, w1.x, accP[q][0]);
                    accP[q][1] = fma2(dy, w1.y, accP[q][1]);
                    accP[q][0] = fma2(dz, w2.x, accP[q][0]);
                    accP[q][1] = fma2(dz, w2.y, accP[q][1]);
                    accP[q][0] = fma2(dw, w3.x, accP[q][0]);
                    accP[q][1] = fma2(dw, w3.y, accP[q][1]);
                }
            }
        }
    }
    #pragma unroll
    for (int cc = 0; cc < 4; cc++) {
        int co = cog*4 + cc;
        float bv = b_last[co];
        int pair = cc >> 1;
        bool high = cc & 1;
        float4 o0, o1;
        o0.x = (high ? hi2(accP[0][pair]) : lo2(accP[0][pair])) + bv;
        o0.y = (high ? hi2(accP[1][pair]) : lo2(accP[1][pair])) + bv;
        o0.z = (high ? hi2(accP[2][pair]) : lo2(accP[2][pair])) + bv;
        o0.w = (high ? hi2(accP[3][pair]) : lo2(accP[3][pair])) + bv;
        o1.x = (high ? hi2(accP[4][pair]) : lo2(accP[4][pair])) + bv;
        o1.y = (high ? hi2(accP[5][pair]) : lo2(accP[5][pair])) + bv;
        o1.z = (high ? hi2(accP[6][pair]) : lo2(accP[6][pair])) + bv;
        o1.w = (high ? hi2(accP[7][pair]) : lo2(accP[7][pair])) + bv;
        float* dst = &out[((b*64 + co)*128 + oh)*128 + owg*8];
        *(float4*)&dst[0] = o0;
        *(float4*)&dst[4] = o1;
    }
}

// ---------------- launcher ----------------
extern "C" void kernel_launch(void* const* d_in, const int* in_sizes, int n_in,
                              void* d_out, int out_size) {
    const float* x      = (const float*)d_in[0];
    const float* w_head = (const float*)d_in[1];
    const float* b_head = (const float*)d_in[2];
    const float* W0     = (const float*)d_in[3];
    const float* a0     = (const float*)d_in[4];
    const float* W1     = (const float*)d_in[5];
    const float* a1     = (const float*)d_in[6];
    const float* W_out  = (const float*)d_in[7];
    const float* a_out  = (const float*)d_in[8];
    const float* w_last = (const float*)d_in[9];
    const float* b_last = (const float*)d_in[10];
    float* out = (float*)d_out;

    prep_kernel<<<216, 256>>>(w_last, w_head, W0, a0, W1, a1, W_out, a_out);  // 0
    conv_proj_kernel<<<256, 256>>>(x, b_head, W0, W1);                        // 1
    dummy_kernel<<<1, 32>>>();                                                // 2
    knn_part_kernel<<<(NTOT/128)*JSPLIT, 128>>>();                            // 3 (profiled)
    gat_mid_kernel<<<NTOT/16, 256>>>(W_out);                                  // 4
    aggout_kernel<<<NTOT/4, 256>>>();                                         // 5
    convt_kernel<<<NB*128, 256>>>(b_last, out);                               // 6
}

// round 17
// speedup vs baseline: 1.6864x; 1.0049x over previous
#include <cuda_runtime.h>
#include <cuda_bf16.h>

typedef unsigned long long ull;

#define NB 2
#define NPB 4096
#define NTOT (NB*NPB)
#define JSPLIT 16
#define JRANGE (NPB/JSPLIT)   // 256
#define JT 128                // j rows staged in smem per step

// ---------------- scratch ----------------
__device__ float g_y[NTOT*64];
__device__ float g_sq[NTOT];
__device__ int   g_nbr[NTOT*7];
__device__ ull   g_part[NTOT*JSPLIT*7];   // partial top-7 keys
__device__ float g_h0[NTOT*64], g_h1[NTOT*64];
__device__ float g_f10[NTOT], g_f20[NTOT], g_f11[NTOT], g_f21[NTOT];
__device__ float g_ho[NTOT*64];
__device__ float g_f1o[NTOT], g_f2o[NTOT];
__device__ float g_outn[NTOT*64];
__device__ float g_wt[9*64*64];      // convT weights [k][ci][co]
__device__ float g_wc[31*9*64];      // conv-head weights [ci*9+k][co]
__device__ float g_va[4*64];         // folded attention vecs heads 0/1
__device__ float g_vaO[2*128];       // folded attention vecs out head

__device__ __forceinline__ ull fma2(ull a, ull b, ull c) {
    ull d;
    asm("fma.rn.f32x2 %0, %1, %2, %3;" : "=l"(d) : "l"(a), "l"(b), "l"(c));
    return d;
}
__device__ __forceinline__ ull add2(ull a, ull b) {
    ull d;
    asm("add.rn.f32x2 %0, %1, %2;" : "=l"(d) : "l"(a), "l"(b));
    return d;
}
__device__ __forceinline__ float sum2(ull v) {
    return __uint_as_float((unsigned)(v & 0xffffffffull))
         + __uint_as_float((unsigned)(v >> 32));
}
__device__ __forceinline__ ull dup2(float v) {
    ull r;
    asm("mov.b64 %0, {%1, %1};" : "=l"(r) : "r"(__float_as_uint(v)));
    return r;
}
__device__ __forceinline__ float lo2(ull v) { return __uint_as_float((unsigned)(v & 0xffffffffull)); }
__device__ __forceinline__ float hi2(ull v) { return __uint_as_float((unsigned)(v >> 32)); }

// ---------------- K0: prep (repacks + folded attention vectors) ----------------
__global__ void prep_kernel(const float* __restrict__ w_last,
                            const float* __restrict__ w_head,
                            const float* __restrict__ W0, const float* __restrict__ a0,
                            const float* __restrict__ W1, const float* __restrict__ a1,
                            const float* __restrict__ W_out, const float* __restrict__ a_out) {
    int idx = blockIdx.x * 256 + threadIdx.x;
    if (idx < 36864) {
        int co = idx & 63, ci = (idx >> 6) & 63, k = idx >> 12;
        g_wt[(k*64 + ci)*64 + co] = w_last[(ci*64 + co)*9 + k];
    } else if (idx < 36864 + 17856) {
        int j = idx - 36864;          // j = (ci*9+k)*64+co
        int co = j & 63, rest = j >> 6;
        int k = rest % 9, ci = rest / 9;
        g_wc[j] = w_head[(co*31 + ci)*9 + k];
    } else if (idx < 36864 + 17856 + 256) {
        int j = idx - 54720;
        int head = j >> 7, which = (j >> 6) & 1, k = j & 63;
        const float* W = head ? W1 : W0;
        const float* a = head ? a1 : a0;
        float s = 0.f;
        for (int c = 0; c < 64; c++) s += W[k*64 + c] * a[which*64 + c];
        g_va[(head*2 + which)*64 + k] = s;
    } else if (idx < 36864 + 17856 + 512) {
        int j = idx - 54976;
        int which = j >> 7, k = j & 127;
        float s = 0.f;
        for (int c = 0; c < 64; c++) s += W_out[k*64 + c] * a_out[which*64 + c];
        g_vaO[which*128 + k] = s;
    }
}

// ---------------- K1: fused conv head + squared norms + proj heads 0/1 ----------------
__global__ void conv_proj_kernel(const float* __restrict__ x,
                                 const float* __restrict__ bias,
                                 const float* __restrict__ W0,
                                 const float* __restrict__ W1) {
    __shared__ float ys[32*68];       // 8,704 B  (y slab, node-major)
    __shared__ float buf[64*136];     // 34,816 B (union: sIn / Wc)
    int blk = blockIdx.x;             // b(1) | oh(6) | half(1)
    int b = blk >> 7;
    int oh = (blk >> 1) & 63;
    int half = blk & 1;
    int ow0 = half * 32;
    int t = threadIdx.x;              // 256

    for (int idx = t; idx < 31*3*66; idx += 256) {
        int iwp = idx % 66;
        int rem = idx / 66;
        int r = rem % 3, ci = rem / 3;
        int ih = oh*2 - 1 + r, iw = ow0*2 - 1 + iwp;
        float v = 0.f;
        if ((unsigned)ih < 128u && (unsigned)iw < 128u)
            v = x[((b*31 + ci)*128 + ih)*128 + iw];
        buf[idx] = v;
    }
    __syncthreads();

    // conv phase, f32x2-packed accumulators
    int cog = t & 15, owg = t >> 4;
    ull accP[2][2];
    #pragma unroll
    for (int q = 0; q < 2; q++) { accP[q][0] = 0ull; accP[q][1] = 0ull; }
    for (int ci = 0; ci < 31; ci++) {
        #pragma unroll
        for (int r = 0; r < 3; r++) {
            int ib = (ci*3 + r)*66 + owg*4;
            #pragma unroll
            for (int kw = 0; kw < 3; kw++) {
                ulonglong2 wv = *(const ulonglong2*)&g_wc[((ci*9 + r*3 + kw)*64) + cog*4];
                #pragma unroll
                for (int q = 0; q < 2; q++) {
                    ull iv = dup2(buf[ib + 2*q + kw]);
                    accP[q][0] = fma2(iv, wv.x, accP[q][0]);
                    accP[q][1] = fma2(iv, wv.y, accP[q][1]);
                }
            }
        }
    }
    float4 bv = *(const float4*)&bias[cog*4];
    float ssq[2];
    #pragma unroll
    for (int q = 0; q < 2; q++) {
        int node = b*4096 + oh*64 + ow0 + owg*2 + q;
        float4 o;
        o.x = lo2(accP[q][0]) + bv.x; o.y = hi2(accP[q][0]) + bv.y;
        o.z = lo2(accP[q][1]) + bv.z; o.w = hi2(accP[q][1]) + bv.w;
        *(float4*)&g_y[node*64 + cog*4] = o;
        *(float4*)&ys[(owg*2 + q)*68 + cog*4] = o;
        ssq[q] = o.x*o.x + o.y*o.y + o.z*o.z + o.w*o.w;
    }
    #pragma unroll
    for (int off = 1; off <= 8; off <<= 1)
        #pragma unroll
        for (int q = 0; q < 2; q++)
            ssq[q] += __shfl_xor_sync(0xffffffffu, ssq[q], off);
    if (cog == 0) {
        #pragma unroll
        for (int q = 0; q < 2; q++)
            g_sq[b*4096 + oh*64 + ow0 + owg*2 + q] = ssq[q];
    }
    __syncthreads();

    for (int idx = t; idx < 64*136; idx += 256) {
        int k = idx / 136, c = idx % 136;
        float v = 0.f;
        if (c < 64) v = W0[k*64 + c];
        else if (c < 128) v = W1[k*64 + c - 64];
        else if (c < 132) v = g_va[(c - 128)*64 + k];
        buf[idx] = v;
    }
    __syncthreads();

    int i0 = b*4096 + oh*64 + ow0;
    int cg = t & 31, ng = t >> 5;
    float pacc[4][5];
    #pragma unroll
    for (int nn = 0; nn < 4; nn++)
        #pragma unroll
        for (int m = 0; m < 5; m++) pacc[nn][m] = 0.f;
    for (int k = 0; k < 64; k++) {
        float w0 = buf[k*136 + cg];
        float w1 = buf[k*136 + cg + 32];
        float w2 = buf[k*136 + cg + 64];
        float w3 = buf[k*136 + cg + 96];
        float w4 = (cg < 4) ? buf[k*136 + 128 + cg] : 0.f;
        #pragma unroll
        for (int nn = 0; nn < 4; nn++) {
            float yv = ys[(ng*4 + nn)*68 + k];
            pacc[nn][0] += yv*w0; pacc[nn][1] += yv*w1;
            pacc[nn][2] += yv*w2; pacc[nn][3] += yv*w3;
            pacc[nn][4] += yv*w4;
        }
    }
    #pragma unroll
    for (int nn = 0; nn < 4; nn++) {
        int node = i0 + ng*4 + nn;
        g_h0[node*64 + cg]      = pacc[nn][0];
        g_h0[node*64 + cg + 32] = pacc[nn][1];
        g_h1[node*64 + cg]      = pacc[nn][2];
        g_h1[node*64 + cg + 32] = pacc[nn][3];
        if (cg == 0) g_f10[node] = pacc[nn][4];
        else if (cg == 1) g_f20[node] = pacc[nn][4];
        else if (cg == 2) g_f11[node] = pacc[nn][4];
        else if (cg == 3) g_f21[node] = pacc[nn][4];
    }
}

// ---------------- K3: kNN partials — register i-row, JSPLIT 16 ----------------
__global__ void __launch_bounds__(128, 4) knn_part_kernel() {
    __shared__ __align__(16) float yj[JT*64];   // 32KB, broadcast-only access
    __shared__ float sqj[JT];
    int t = threadIdx.x;                        // 128
    int ic = blockIdx.x >> 4;                   // 64 i-chunks of 128 rows
    int js = blockIdx.x & 15;
    int i0 = ic * 128;
    int i = i0 + t;
    int jsbase = js * JRANGE;
    int jbase = (i0 & ~4095) + jsbase;

    ulonglong2 yiv[16];
    #pragma unroll
    for (int c4 = 0; c4 < 16; c4++)
        yiv[c4] = *(const ulonglong2*)&g_y[i*64 + c4*4];
    float si = g_sq[i];

    ull ktop[7];
    const ull SENT = ((ull)0x7F7FFFFFull << 32) | 0x7FFFFFFFull;
    #pragma unroll
    for (int s = 0; s < 7; s++) ktop[s] = SENT;
    float bd6 = 3.4028235e38f;

    for (int jt0 = 0; jt0 < JRANGE; jt0 += JT) {
        __syncthreads();
        for (int idx = t; idx < JT*16; idx += 128) {
            int row = idx >> 4, c4 = idx & 15;
            *(float4*)&yj[row*64 + c4*4] = *(const float4*)&g_y[(jbase + jt0 + row)*64 + c4*4];
        }
        if (t < JT) sqj[t] = g_sq[jbase + jt0 + t];
        __syncthreads();

        for (int jl = 0; jl < JT; jl += 2) {
            const ulonglong2* p0 = (const ulonglong2*)&yj[jl*64];
            const ulonglong2* p1 = (const ulonglong2*)&yj[(jl+1)*64];
            ull a0e = 0, a0o = 0, a1e = 0, a1o = 0;
            #pragma unroll
            for (int c2 = 0; c2 < 16; c2++) {
                ulonglong2 u0 = p0[c2];
                ulonglong2 u1 = p1[c2];
                a0e = fma2(yiv[c2].x, u0.x, a0e);
                a0o = fma2(yiv[c2].y, u0.y, a0o);
                a1e = fma2(yiv[c2].x, u1.x, a1e);
                a1o = fma2(yiv[c2].y, u1.y, a1o);
            }
            ull s0 = add2(a0e, a0o);
            ull s1 = add2(a1e, a1o);
            float dot0 = lo2(s0) + hi2(s0);
            float dot1 = lo2(s1) + hi2(s1);
            float d0 = fmaxf(fmaf(-2.f, dot0, si + sqj[jl]),   0.f);
            float d1 = fmaxf(fmaf(-2.f, dot1, si + sqj[jl+1]), 0.f);
            int j0 = jsbase + jt0 + jl;   // j within batch, ascending scan
            // ascending-j + strict-less float gate == stable tie-break
            if (d0 < bd6) {
                ull key = ((ull)__float_as_uint(d0) << 32) | (unsigned)j0;
                ktop[6] = key;
                #pragma unroll
                for (int s = 5; s >= 0; s--)
                    if (ktop[s+1] < ktop[s]) { ull tm = ktop[s]; ktop[s] = ktop[s+1]; ktop[s+1] = tm; }
                bd6 = __uint_as_float((unsigned)(ktop[6] >> 32));
            }
            if (d1 < bd6) {
                ull key = ((ull)__float_as_uint(d1) << 32) | (unsigned)(j0 + 1);
                ktop[6] = key;
                #pragma unroll
                for (int s = 5; s >= 0; s--)
                    if (ktop[s+1] < ktop[s]) { ull tm = ktop[s]; ktop[s] = ktop[s+1]; ktop[s+1] = tm; }
                bd6 = __uint_as_float((unsigned)(ktop[6] >> 32));
            }
        }
    }
    #pragma unroll
    for (int s = 0; s < 7; s++)
        g_part[(i*JSPLIT + js)*7 + s] = ktop[s];
}

// ---------------- K5: fused merge + attention agg heads 0/1 + out-head projection ----------------
__global__ void gat_mid_kernel(const float* __restrict__ W_out) {
    __shared__ float Wo[128*72];     // 36,864 B
    __shared__ float hs[16*136];     //  8,704 B
    __shared__ int   snbr[16][7];
    __shared__ float satt[16][2][7];
    int t = threadIdx.x;             // 256
    int i0 = blockIdx.x * 16;
    int bb = i0 & ~4095;

    if (t < 16) {
        int node = i0 + t;
        ull best[7];
        #pragma unroll
        for (int s = 0; s < 7; s++) best[s] = 0xFFFFFFFFFFFFFFFFull;
        for (int js = 0; js < JSPLIT; js++) {
            const ull* pp = &g_part[(node*JSPLIT + js)*7];
            #pragma unroll
            for (int s = 0; s < 7; s++) {
                ull k = pp[s];
                if (k < best[6]) {
                    best[6] = k;
                    #pragma unroll
                    for (int q = 5; q >= 0; q--)
                        if (best[q+1] < best[q]) { ull tm = best[q]; best[q] = best[q+1]; best[q+1] = tm; }
                }
            }
        }
        #pragma unroll
        for (int s = 0; s < 7; s++) {
            int j = (int)(unsigned)(best[s] & 0xffffffffull);
            snbr[t][s] = j;
            g_nbr[node*7 + s] = j;
        }
    }
    for (int idx = t; idx < 128*72; idx += 256) {
        int k = idx / 72, c = idx % 72;
        float v = 0.f;
        if (c < 64) v = W_out[k*64 + c];
        else if (c == 64) v = g_vaO[k];
        else if (c == 65) v = g_vaO[128 + k];
        Wo[idx] = v;
    }
    __syncthreads();

    if (t < 32) {
        int n = t >> 1, head = t & 1;
        int node = i0 + n;
        const float* f1 = head ? g_f11 : g_f10;
        const float* f2 = head ? g_f21 : g_f20;
        float fi = f1[node];
        float e[7], m = -3.4e38f;
        #pragma unroll
        for (int s = 0; s < 7; s++) {
            float v = fi + f2[bb + snbr[n][s]];
            v = v > 0.f ? v : 0.2f*v;
            e[s] = v; if (v > m) m = v;
        }
        float sum = 0.f;
        #pragma unroll
        for (int s = 0; s < 7; s++) { e[s] = expf(e[s] - m); sum += e[s]; }
        float inv = 1.f / sum;
        #pragma unroll
        for (int s = 0; s < 7; s++) satt[n][head][s] = e[s]*inv;
    }
    __syncthreads();

    for (int idx = t; idx < 2048; idx += 256) {
        int n = idx >> 7, q = idx & 127;
        int head = q >> 6, c = q & 63;
        const float* h = head ? g_h1 : g_h0;
        float acc = 0.f;
        #pragma unroll
        for (int s = 0; s < 7; s++)
            acc += satt[n][head][s] * h[(bb + snbr[n][s])*64 + c];
        acc = acc > 0.f ? acc : 0.f;
        hs[n*136 + q] = acc;
    }
    __syncthreads();

    int cg = t & 31, ng = t >> 5;
    float acc[2][3];
    #pragma unroll
    for (int nn = 0; nn < 2; nn++)
        #pragma unroll
        for (int m = 0; m < 3; m++) acc[nn][m] = 0.f;
    for (int k = 0; k < 128; k++) {
        float w0 = Wo[k*72 + cg];
        float w1 = Wo[k*72 + cg + 32];
        float w2 = (cg < 2) ? Wo[k*72 + 64 + cg] : 0.f;
        #pragma unroll
        for (int nn = 0; nn < 2; nn++) {
            float yv = hs[(ng*2 + nn)*136 + k];
            acc[nn][0] += yv*w0; acc[nn][1] += yv*w1; acc[nn][2] += yv*w2;
        }
    }
    #pragma unroll
    for (int nn = 0; nn < 2; nn++) {
        int node = i0 + ng*2 + nn;
        g_ho[node*64 + cg]      = acc[nn][0];
        g_ho[node*64 + cg + 32] = acc[nn][1];
        if (cg == 0) g_f1o[node] = acc[nn][2];
        else if (cg == 1) g_f2o[node] = acc[nn][2];
    }
}

// ---------------- K7: out-head agg + elu + log_softmax ----------------
__global__ void aggout_kernel() {
    __shared__ float wmax[4][2];
    __shared__ float wsum[4][2];
    int t = threadIdx.x;
    int ln = t >> 6, c = t & 63;
    int node = blockIdx.x*4 + ln;
    int lane = t & 31, wh = (t >> 5) & 1;
    int bb = node & ~4095;
    int nb[7];
    #pragma unroll
    for (int s = 0; s < 7; s++) nb[s] = bb + g_nbr[node*7 + s];
    float fi = g_f1o[node];
    float e[7], m = -3.4e38f;
    #pragma unroll
    for (int s = 0; s < 7; s++) {
        float v = fi + g_f2o[nb[s]];
        v = v > 0.f ? v : 0.2f*v;
        e[s] = v; if (v > m) m = v;
    }
    float sum = 0.f;
    #pragma unroll
    for (int s = 0; s < 7; s++) { e[s] = expf(e[s] - m); sum += e[s]; }
    float inv = 1.f / sum;
    float acc = 0.f;
    #pragma unroll
    for (int s = 0; s < 7; s++) acc += e[s]*inv * g_ho[nb[s]*64 + c];
    float v = acc > 0.f ? acc : (expf(acc) - 1.f);

    float mx = v;
    #pragma unroll
    for (int off = 16; off; off >>= 1) mx = fmaxf(mx, __shfl_down_sync(0xffffffffu, mx, off));
    if (lane == 0) wmax[ln][wh] = mx;
    __syncthreads();
    mx = fmaxf(wmax[ln][0], wmax[ln][1]);
    float p = expf(v - mx);
    float ssum = p;
    #pragma unroll
    for (int off = 16; off; off >>= 1) ssum += __shfl_down_sync(0xffffffffu, ssum, off);
    if (lane == 0) wsum[ln][wh] = ssum;
    __syncthreads();
    float tot = wsum[ln][0] + wsum[ln][1];
    g_outn[node*64 + c] = v - mx - logf(tot);
}

// ---------------- K8: ConvTranspose2d (f32x2-packed register tiling) ----------------
__global__ void convt_kernel(const float* __restrict__ b_last, float* __restrict__ out) {
    int b = blockIdx.x >> 7;
    int oh = blockIdx.x & 127;
    __shared__ __align__(16) float sin[2][64*68];
    int khs[2], ihs[2];
    int cnt = 0;
    for (int kh = 0; kh < 3; kh++) {
        int num = oh + 1 - kh;
        if (num & 1) continue;
        int ih = num >> 1;
        if (ih < 0 || ih >= 64) continue;
        khs[cnt] = kh; ihs[cnt] = ih; cnt++;
    }
    int t = threadIdx.x;
    for (int r = 0; r < cnt; r++) {
        const float* src = &g_outn[((b << 12) + ihs[r]*64)*64];
        for (int idx = t; idx < 1024; idx += 256) {
            int iw = idx >> 4, c4 = idx & 15;
            *(float4*)&sin[r][iw*68 + c4*4] = *(const float4*)&src[iw*64 + c4*4];
        }
    }
    __syncthreads();
    int cog = t & 15, owg = t >> 4;
    ull accP[8][2];
    #pragma unroll
    for (int q = 0; q < 8; q++) { accP[q][0] = 0ull; accP[q][1] = 0ull; }

    for (int r = 0; r < cnt; r++) {
        int kh = khs[r];
        #pragma unroll
        for (int kw = 0; kw < 3; kw++) {
            int iwq[4]; bool vq[4];
            #pragma unroll
            for (int u = 0; u < 4; u++) {
                int q = ((kw + 1) & 1) + 2*u;
                int num = owg*8 + q + 1 - kw;
                int iw = num >> 1;
                iwq[u] = iw;
                vq[u] = (num >= 0) && (iw < 64);
            }
            const float* wbase = &g_wt[(kh*3 + kw)*4096 + cog*4];
            for (int ci0 = 0; ci0 < 64; ci0 += 4) {
                ulonglong2 w0 = *(const ulonglong2*)&wbase[(ci0+0)*64];
                ulonglong2 w1 = *(const ulonglong2*)&wbase[(ci0+1)*64];
                ulonglong2 w2 = *(const ulonglong2*)&wbase[(ci0+2)*64];
                ulonglong2 w3 = *(const ulonglong2*)&wbase[(ci0+3)*64];
                #pragma unroll
                for (int u = 0; u < 4; u++) {
                    if (!vq[u]) continue;
                    int q = ((kw + 1) & 1) + 2*u;
                    float4 iv = *(const float4*)&sin[r][iwq[u]*68 + ci0];
                    ull dx = dup2(iv.x), dy = dup2(iv.y), dz = dup2(iv.z), dw = dup2(iv.w);
                    accP[q][0] = fma2(dx, w0.x, accP[q][0]);
                    accP[q][1] = fma2(dx, w0.y, accP[q][1]);
                    accP[q][0] = fma2(dy, w1.x, accP[q][0]);
                    accP[q][1] = fma2(dy, w1.y, accP[q][1]);
                    accP[q][0] = fma2(dz, w2.x, accP[q][0]);
                    accP[q][1] = fma2(dz, w2.y, accP[q][1]);
                    accP[q][0] = fma2(dw, w3.x, accP[q][0]);
                    accP[q][1] = fma2(dw, w3.y, accP[q][1]);
                }
            }
        }
    }
    #pragma unroll
    for (int cc = 0; cc < 4; cc++) {
        int co = cog*4 + cc;
        float bv = b_last[co];
        int pair = cc >> 1;
        bool high = cc & 1;
        float4 o0, o1;
        o0.x = (high ? hi2(accP[0][pair]) : lo2(accP[0][pair])) + bv;
        o0.y = (high ? hi2(accP[1][pair]) : lo2(accP[1][pair])) + bv;
        o0.z = (high ? hi2(accP[2][pair]) : lo2(accP[2][pair])) + bv;
        o0.w = (high ? hi2(accP[3][pair]) : lo2(accP[3][pair])) + bv;
        o1.x = (high ? hi2(accP[4][pair]) : lo2(accP[4][pair])) + bv;
        o1.y = (high ? hi2(accP[5][pair]) : lo2(accP[5][pair])) + bv;
        o1.z = (high ? hi2(accP[6][pair]) : lo2(accP[6][pair])) + bv;
        o1.w = (high ? hi2(accP[7][pair]) : lo2(accP[7][pair])) + bv;
        float* dst = &out[((b*64 + co)*128 + oh)*128 + owg*8];
        *(float4*)&dst[0] = o0;
        *(float4*)&dst[4] = o1;
    }
}

// ---------------- launcher ----------------
extern "C" void kernel_launch(void* const* d_in, const int* in_sizes, int n_in,
                              void* d_out, int out_size) {
    const float* x      = (const float*)d_in[0];
    const float* w_head = (const float*)d_in[1];
    const float* b_head = (const float*)d_in[2];
    const float* W0     = (const float*)d_in[3];
    const float* a0     = (const float*)d_in[4];
    const float* W1     = (const float*)d_in[5];
    const float* a1     = (const float*)d_in[6];
    const float* W_out  = (const float*)d_in[7];
    const float* a_out  = (const float*)d_in[8];
    const float* w_last = (const float*)d_in[9];
    const float* b_last = (const float*)d_in[10];
    float* out = (float*)d_out;

    prep_kernel<<<216, 256>>>(w_last, w_head, W0, a0, W1, a1, W_out, a_out);  // 0
    conv_proj_kernel<<<256, 256>>>(x, b_head, W0, W1);                        // 1
    knn_part_kernel<<<(NTOT/128)*JSPLIT, 128>>>();                            // 2
    gat_mid_kernel<<<NTOT/16, 256>>>(W_out);                                  // 3 (profiled)
    aggout_kernel<<<NTOT/4, 256>>>();                                         // 4
    convt_kernel<<<NB*128, 256>>>(b_last, out);                               // 5
}